// round 9
// baseline (speedup 1.0000x reference)
#include <cuda_runtime.h>
#include <cstdint>

#define NU 100000
#define NI 50000
#define CH 128
#define NE 600000
#define NLAY 2

// ---------------- scratch (device globals; no allocation allowed) ------------
__device__ float g_xu[NU * CH];
__device__ float g_xi[NI * CH];
__device__ float g_agg_u[NU * CH];
__device__ float g_agg_i[NI * CH];
__device__ float g_t1u[NU * CH];
__device__ float g_t2u[NU * CH];
__device__ float g_t1i[NI * CH];
__device__ float g_t2i[NI * CH];

// ---------------- packed f32x2 helpers ---------------------------------------
__device__ __forceinline__ unsigned long long pk2(float x, float y) {
    unsigned long long r;
    asm("mov.b64 %0, {%1, %2};" : "=l"(r) : "f"(x), "f"(y));
    return r;
}
__device__ __forceinline__ void fma2(unsigned long long& d, unsigned long long a,
                                     unsigned long long b) {
    asm("fma.rn.f32x2 %0, %1, %2, %0;" : "+l"(d) : "l"(a), "l"(b));
}
__device__ __forceinline__ void upk(unsigned long long v, float& lo, float& hi) {
    asm("mov.b64 {%0, %1}, %2;" : "=f"(lo), "=f"(hi) : "l"(v));
}

// ---------------- GEMM: Y[M,128] = act( (alpha*X + AGG) @ W + bias ) ---------
// BM=BN=128, BK=32, 256 threads, 8x8 register tile, f32x2 packed FMA.
__global__ __launch_bounds__(256) void gemm128(
    const float* __restrict__ X, const float* __restrict__ AGG,
    const float* __restrict__ epsp, const float* __restrict__ W,
    const float* __restrict__ bias, float* __restrict__ Y, int M, int do_relu) {
    __shared__ float As[128][32];
    __shared__ float Bs[32][128];

    const int tid = threadIdx.x;
    const int tx = tid & 15;          // 0..15 -> col tile
    const int ty = tid >> 4;          // 0..15 -> row tile
    const int row0 = blockIdx.x * 128 + ty * 8;

    float alpha = 1.0f;
    if (epsp) alpha = 1.0f + __ldg(epsp);

    unsigned long long acc[8][4];
#pragma unroll
    for (int i = 0; i < 8; i++)
#pragma unroll
        for (int j = 0; j < 4; j++) acc[i][j] = 0ULL;

#pragma unroll 1
    for (int kc = 0; kc < 128; kc += 32) {
        // load A tile (with fused (1+eps)*x + agg), rows of this m-tile
#pragma unroll
        for (int q = 0; q < 4; q++) {
            int f = tid + 256 * q;
            int r = f >> 3, c4 = f & 7;
            int grow = blockIdx.x * 128 + r;
            float4 v = make_float4(0.f, 0.f, 0.f, 0.f);
            if (grow < M) {
                v = *(const float4*)(X + (size_t)grow * CH + kc + c4 * 4);
                if (AGG) {
                    const float4 g =
                        *(const float4*)(AGG + (size_t)grow * CH + kc + c4 * 4);
                    v.x = fmaf(alpha, v.x, g.x);
                    v.y = fmaf(alpha, v.y, g.y);
                    v.z = fmaf(alpha, v.z, g.z);
                    v.w = fmaf(alpha, v.w, g.w);
                }
            }
            *(float4*)&As[r][c4 * 4] = v;
        }
        // load B tile (weights, no guard: K=N=128)
#pragma unroll
        for (int q = 0; q < 4; q++) {
            int f = tid + 256 * q;
            int r = f >> 5, c4 = f & 31;
            *(float4*)&Bs[r][c4 * 4] =
                *(const float4*)(W + (size_t)(kc + r) * CH + c4 * 4);
        }
        __syncthreads();

#pragma unroll
        for (int kk = 0; kk < 32; kk++) {
            unsigned long long pa[8];
#pragma unroll
            for (int i = 0; i < 8; i++) {
                float a = As[ty * 8 + i][kk];
                pa[i] = pk2(a, a);
            }
            const ulonglong2 bb0 = *(const ulonglong2*)&Bs[kk][tx * 8];
            const ulonglong2 bb1 = *(const ulonglong2*)&Bs[kk][tx * 8 + 4];
            unsigned long long bq[4] = {bb0.x, bb0.y, bb1.x, bb1.y};
#pragma unroll
            for (int i = 0; i < 8; i++)
#pragma unroll
                for (int j = 0; j < 4; j++) fma2(acc[i][j], pa[i], bq[j]);
        }
        __syncthreads();
    }

    // epilogue: bias (+ relu) + store
    const float4 bv0 = *(const float4*)(bias + tx * 8);
    const float4 bv1 = *(const float4*)(bias + tx * 8 + 4);
    const float bb[8] = {bv0.x, bv0.y, bv0.z, bv0.w, bv1.x, bv1.y, bv1.z, bv1.w};
#pragma unroll
    for (int i = 0; i < 8; i++) {
        int row = row0 + i;
        if (row < M) {
            float y[8];
#pragma unroll
            for (int j = 0; j < 4; j++) upk(acc[i][j], y[2 * j], y[2 * j + 1]);
#pragma unroll
            for (int j = 0; j < 8; j++) {
                y[j] += bb[j];
                if (do_relu) y[j] = fmaxf(y[j], 0.0f);
            }
            float4 o0 = make_float4(y[0], y[1], y[2], y[3]);
            float4 o1 = make_float4(y[4], y[5], y[6], y[7]);
            float* p = Y + (size_t)row * CH + tx * 8;
            *(float4*)p = o0;
            *(float4*)(p + 4) = o1;
        }
    }
}

// ---------------- edge scatter: agg[dst] += x[src], warp per edge ------------
__global__ void edge_scatter(const float* __restrict__ xsrc,
                             const int* __restrict__ esrc,
                             const int* __restrict__ edst,
                             float* __restrict__ agg, int n_edges) {
    int w = (int)((blockIdx.x * (unsigned)blockDim.x + threadIdx.x) >> 5);
    int lane = threadIdx.x & 31;
    if (w >= n_edges) return;
    int s = __ldg(&esrc[w]);
    int d = __ldg(&edst[w]);
    const float4 v = *(const float4*)(xsrc + (size_t)s * CH + lane * 4);
    float* p = agg + (size_t)d * CH + lane * 4;
    asm volatile("red.global.add.v4.f32 [%0], {%1, %2, %3, %4};"
                 :: "l"(p), "f"(v.x), "f"(v.y), "f"(v.z), "f"(v.w)
                 : "memory");
}

// ---------------- LayerNorm (node mode) + ReLU, warp per node ----------------
__global__ void ln_relu(const float* __restrict__ X, const float* __restrict__ g,
                        const float* __restrict__ b, float* __restrict__ Y,
                        int n) {
    int w = (int)((blockIdx.x * (unsigned)blockDim.x + threadIdx.x) >> 5);
    int lane = threadIdx.x & 31;
    if (w >= n) return;
    const float4 v = *(const float4*)(X + (size_t)w * CH + lane * 4);
    float s = v.x + v.y + v.z + v.w;
#pragma unroll
    for (int o = 16; o > 0; o >>= 1) s += __shfl_xor_sync(0xffffffffu, s, o);
    float m = s * (1.0f / CH);
    float dx0 = v.x - m, dx1 = v.y - m, dx2 = v.z - m, dx3 = v.w - m;
    float ss = dx0 * dx0 + dx1 * dx1 + dx2 * dx2 + dx3 * dx3;
#pragma unroll
    for (int o = 16; o > 0; o >>= 1) ss += __shfl_xor_sync(0xffffffffu, ss, o);
    float inv = rsqrtf(ss * (1.0f / CH) + 1e-5f);
    const float4 gv = *(const float4*)(g + lane * 4);
    const float4 bv = *(const float4*)(b + lane * 4);
    float4 o4;
    o4.x = fmaxf(dx0 * inv * gv.x + bv.x, 0.0f);
    o4.y = fmaxf(dx1 * inv * gv.y + bv.y, 0.0f);
    o4.z = fmaxf(dx2 * inv * gv.z + bv.z, 0.0f);
    o4.w = fmaxf(dx3 * inv * gv.w + bv.w, 0.0f);
    *(float4*)(Y + (size_t)w * CH + lane * 4) = o4;
}

// ---------------- orchestration ---------------------------------------------
extern "C" void kernel_launch(void* const* d_in, const int* in_sizes, int n_in,
                              void* d_out, int out_size) {
    const float* x_user = (const float*)d_in[0];
    const float* x_item = (const float*)d_in[1];
    const float* W_init = (const float*)d_in[2];   // (2,128,128)
    const float* b_init = (const float*)d_in[3];   // (2,128)
    const float* mlp_W  = (const float*)d_in[4];   // (L,2,NN,128,128)
    const float* mlp_b  = (const float*)d_in[5];   // (L,2,NN,128)
    const float* eps    = (const float*)d_in[6];   // (L,2)
    const float* ln_g   = (const float*)d_in[7];   // (L,2,128)
    const float* ln_b   = (const float*)d_in[8];   // (L,2,128)
    const int* edge_ui  = (const int*)d_in[9];     // (2,E): [0]=src user, [1]=dst item
    const int* edge_iu  = (const int*)d_in[10];    // (2,E): [0]=src item, [1]=dst user

    float *xu, *xi, *au, *ai, *t1u, *t2u, *t1i, *t2i;
    cudaGetSymbolAddress((void**)&xu, g_xu);
    cudaGetSymbolAddress((void**)&xi, g_xi);
    cudaGetSymbolAddress((void**)&au, g_agg_u);
    cudaGetSymbolAddress((void**)&ai, g_agg_i);
    cudaGetSymbolAddress((void**)&t1u, g_t1u);
    cudaGetSymbolAddress((void**)&t2u, g_t2u);
    cudaGetSymbolAddress((void**)&t1i, g_t1i);
    cudaGetSymbolAddress((void**)&t2i, g_t2i);

    const int gu = (NU + 127) / 128;   // gemm grid users
    const int gi = (NI + 127) / 128;   // gemm grid items
    const int eblk = (NE * 32 + 255) / 256;
    const int lnu = (NU + 7) / 8;
    const int lni = (NI + 7) / 8;

    // init projection (no relu)
    gemm128<<<gu, 256>>>(x_user, nullptr, nullptr, W_init, b_init, xu, NU, 0);
    gemm128<<<gi, 256>>>(x_item, nullptr, nullptr, W_init + 128 * 128,
                         b_init + 128, xi, NI, 0);

    for (int l = 0; l < NLAY; l++) {
        cudaMemsetAsync(ai, 0, (size_t)NI * CH * sizeof(float), 0);
        cudaMemsetAsync(au, 0, (size_t)NU * CH * sizeof(float), 0);
        // user -> item
        edge_scatter<<<eblk, 256>>>(xu, edge_ui, edge_ui + NE, ai, NE);
        // item -> user
        edge_scatter<<<eblk, 256>>>(xi, edge_iu, edge_iu + NE, au, NE);

        // item MLP: edge type 0
        {
            const float* W0 = mlp_W + (size_t)((l * 2 + 0) * 2 + 0) * 128 * 128;
            const float* W1 = mlp_W + (size_t)((l * 2 + 0) * 2 + 1) * 128 * 128;
            const float* B0 = mlp_b + (size_t)((l * 2 + 0) * 2 + 0) * 128;
            const float* B1 = mlp_b + (size_t)((l * 2 + 0) * 2 + 1) * 128;
            gemm128<<<gi, 256>>>(xi, ai, eps + l * 2 + 0, W0, B0, t1i, NI, 1);
            gemm128<<<gi, 256>>>(t1i, nullptr, nullptr, W1, B1, t2i, NI, 1);
        }
        // user MLP: edge type 1
        {
            const float* W0 = mlp_W + (size_t)((l * 2 + 1) * 2 + 0) * 128 * 128;
            const float* W1 = mlp_W + (size_t)((l * 2 + 1) * 2 + 1) * 128 * 128;
            const float* B0 = mlp_b + (size_t)((l * 2 + 1) * 2 + 0) * 128;
            const float* B1 = mlp_b + (size_t)((l * 2 + 1) * 2 + 1) * 128;
            gemm128<<<gu, 256>>>(xu, au, eps + l * 2 + 1, W0, B0, t1u, NU, 1);
            gemm128<<<gu, 256>>>(t1u, nullptr, nullptr, W1, B1, t2u, NU, 1);
        }

        float* ou = (l == NLAY - 1) ? (float*)d_out : xu;
        float* oi = (l == NLAY - 1) ? (float*)d_out + (size_t)NU * CH : xi;
        // node type 0 = user, 1 = item
        ln_relu<<<lnu, 256>>>(t2u, ln_g + (l * 2 + 0) * 128,
                              ln_b + (l * 2 + 0) * 128, ou, NU);
        ln_relu<<<lni, 256>>>(t2i, ln_g + (l * 2 + 1) * 128,
                              ln_b + (l * 2 + 1) * 128, oi, NI);
    }
}

// round 11
// speedup vs baseline: 1.6058x; 1.6058x over previous
#include <cuda_runtime.h>
#include <cstdint>

#define NU 100000
#define NI 50000
#define CH 128
#define NE 600000
#define NLAY 2
#define TU ((NU + 127) / 128)
#define TI ((NI + 127) / 128)

// ---------------- scratch (device globals; no allocation allowed) ------------
__device__ float g_xu[NU * CH];
__device__ float g_xi[NI * CH];
__device__ float g_agg_u[NU * CH];
__device__ float g_agg_i[NI * CH];
__device__ float g_t1u[NU * CH];
__device__ float g_t2u[NU * CH];
__device__ float g_t1i[NI * CH];
__device__ float g_t2i[NI * CH];
// weights, bf16 hi/lo split, [10][128][128] bf16 packed as u32 pairs along n
__device__ unsigned g_W_hi[10 * 8192];
__device__ unsigned g_W_lo[10 * 8192];

// ---------------- bf16 split helpers -----------------------------------------
__device__ __forceinline__ unsigned packbf(float a, float b) {  // lo=a, hi=b
    unsigned r;
    asm("cvt.rn.satfinite.bf16x2.f32 %0, %1, %2;" : "=r"(r) : "f"(b), "f"(a));
    return r;
}
__device__ __forceinline__ float bflo(unsigned p) { return __uint_as_float(p << 16); }
__device__ __forceinline__ float bfhi(unsigned p) { return __uint_as_float(p & 0xffff0000u); }

__device__ __forceinline__ unsigned smem_u32(const void* p) {
    unsigned a;
    asm("{ .reg .u64 t; cvta.to.shared.u64 t, %1; cvt.u32.u64 %0, t; }"
        : "=r"(a) : "l"(p));
    return a;
}
__device__ __forceinline__ void ldsm_x4(unsigned& r0, unsigned& r1, unsigned& r2,
                                        unsigned& r3, unsigned addr) {
    asm volatile("ldmatrix.sync.aligned.m8n8.x4.shared.b16 {%0,%1,%2,%3}, [%4];"
                 : "=r"(r0), "=r"(r1), "=r"(r2), "=r"(r3) : "r"(addr));
}
__device__ __forceinline__ void ldsm_x2t(unsigned& r0, unsigned& r1, unsigned addr) {
    asm volatile("ldmatrix.sync.aligned.m8n8.x2.trans.shared.b16 {%0,%1}, [%2];"
                 : "=r"(r0), "=r"(r1) : "r"(addr));
}
__device__ __forceinline__ void mma16816(float* d, const unsigned* a, const unsigned* b) {
    asm volatile(
        "mma.sync.aligned.m16n8k16.row.col.f32.bf16.bf16.f32 "
        "{%0,%1,%2,%3}, {%4,%5,%6,%7}, {%8,%9}, {%0,%1,%2,%3};"
        : "+f"(d[0]), "+f"(d[1]), "+f"(d[2]), "+f"(d[3])
        : "r"(a[0]), "r"(a[1]), "r"(a[2]), "r"(a[3]), "r"(b[0]), "r"(b[1]));
}

// swizzled chunk index (16B units) for a 128x128 bf16 tile: row r, 16B-chunk c
__device__ __forceinline__ int swz(int r, int c) { return r * 16 + (c ^ (r & 7)); }

// ---------------- convW: bf16 hi/lo split of 10 weight matrices --------------
__global__ void convW(const float* __restrict__ W_init, const float* __restrict__ mlp_W,
                      unsigned* __restrict__ Whi, unsigned* __restrict__ Wlo) {
    const int m = blockIdx.x;  // 0..9
    const float* W = (m < 2) ? (W_init + (size_t)m * CH * CH)
                             : (mlp_W + (size_t)(m - 2) * CH * CH);
    for (int t = threadIdx.x; t < 8192; t += blockDim.x) {
        float w0 = W[2 * t], w1 = W[2 * t + 1];
        unsigned hi = packbf(w0, w1);
        unsigned lo = packbf(w0 - bflo(hi), w1 - bfhi(hi));
        Whi[m * 8192 + t] = hi;
        Wlo[m * 8192 + t] = lo;
    }
}

// ---------------- tensor-core GEMM: Y = act((alpha*X+AGG) @ W + bias) --------
// CTA = 128x128 tile, 8 warps (2x4), mma.sync m16n8k16 bf16, 3-term split.
#define SMW_HI 0
#define SMW_LO 32768
#define SMA_HI 65536
#define SMA_LO 98304
#define SM_BIAS 131072
#define SM_TOT (131072 + 512)

__global__ __launch_bounds__(256) void mma_gemm(
    const float* __restrict__ X, const float* __restrict__ AGG,
    const float* __restrict__ epsp,
    const unsigned* __restrict__ Whi, const unsigned* __restrict__ Wlo,
    const float* __restrict__ bias, float* __restrict__ Y, int M, int do_relu) {
    extern __shared__ char sm[];
    const int tid = threadIdx.x, wid = tid >> 5, lane = tid & 31;
    const int row0 = blockIdx.x * 128;
    const float alpha = epsp ? (1.0f + __ldg(epsp)) : 1.0f;

    // ---- load W hi/lo into swizzled SMEM (global chunk index == linear) ----
    {
        const uint4* gh = (const uint4*)Whi;
        const uint4* gl = (const uint4*)Wlo;
        uint4* sh = (uint4*)(sm + SMW_HI);
        uint4* sl = (uint4*)(sm + SMW_LO);
#pragma unroll
        for (int q = 0; q < 8; q++) {
            int c = tid + 256 * q;
            int r = c >> 4, ch = c & 15;
            int d = swz(r, ch);
            sh[d] = gh[c];
            sl[d] = gl[c];
        }
    }
    // ---- load A (fp32, fused alpha*x+agg) -> bf16 hi/lo swizzled SMEM ----
    {
        uint4* sh = (uint4*)(sm + SMA_HI);
        uint4* sl = (uint4*)(sm + SMA_LO);
#pragma unroll
        for (int q = 0; q < 8; q++) {
            int c = tid + 256 * q;
            int r = c >> 4, ch = c & 15;
            int grow = row0 + r;
            float v[8];
#pragma unroll
            for (int j = 0; j < 8; j++) v[j] = 0.0f;
            if (grow < M) {
                const float4* p = (const float4*)(X + (size_t)grow * CH + ch * 8);
                float4 v0 = p[0], v1 = p[1];
                if (AGG) {
                    const float4* g = (const float4*)(AGG + (size_t)grow * CH + ch * 8);
                    float4 g0 = g[0], g1 = g[1];
                    v0.x = fmaf(alpha, v0.x, g0.x); v0.y = fmaf(alpha, v0.y, g0.y);
                    v0.z = fmaf(alpha, v0.z, g0.z); v0.w = fmaf(alpha, v0.w, g0.w);
                    v1.x = fmaf(alpha, v1.x, g1.x); v1.y = fmaf(alpha, v1.y, g1.y);
                    v1.z = fmaf(alpha, v1.z, g1.z); v1.w = fmaf(alpha, v1.w, g1.w);
                }
                v[0] = v0.x; v[1] = v0.y; v[2] = v0.z; v[3] = v0.w;
                v[4] = v1.x; v[5] = v1.y; v[6] = v1.z; v[7] = v1.w;
            }
            unsigned hi[4], lo[4];
#pragma unroll
            for (int j = 0; j < 4; j++) {
                hi[j] = packbf(v[2 * j], v[2 * j + 1]);
                lo[j] = packbf(v[2 * j] - bflo(hi[j]), v[2 * j + 1] - bfhi(hi[j]));
            }
            int d = swz(r, ch);
            sh[d] = make_uint4(hi[0], hi[1], hi[2], hi[3]);
            sl[d] = make_uint4(lo[0], lo[1], lo[2], lo[3]);
        }
    }
    if (tid < 128) ((float*)(sm + SM_BIAS))[tid] = bias[tid];
    __syncthreads();

    const int wm = wid & 1;       // 0..1 -> 64-row half
    const int wn = wid >> 1;      // 0..3 -> 32-col quarter
    const unsigned base = smem_u32(sm);

    float acc[4][4][4];
#pragma unroll
    for (int mi = 0; mi < 4; mi++)
#pragma unroll
        for (int ni = 0; ni < 4; ni++)
#pragma unroll
            for (int j = 0; j < 4; j++) acc[mi][ni][j] = 0.0f;

    // 3 passes: (Ahi,Whi), (Ahi,Wlo), (Alo,Whi)
#pragma unroll
    for (int pass = 0; pass < 3; pass++) {
        const unsigned Ab = base + ((pass == 2) ? SMA_LO : SMA_HI);
        const unsigned Bb = base + ((pass == 1) ? SMW_LO : SMW_HI);
#pragma unroll
        for (int ks = 0; ks < 8; ks++) {
            // B fragments: 4 n-tiles (k-rows, trans)
            unsigned bfr[4][2];
            const int krow = ks * 16 + (lane & 15);
#pragma unroll
            for (int ni = 0; ni < 4; ni++) {
                const int chunk = wn * 4 + ni;
                ldsm_x2t(bfr[ni][0], bfr[ni][1], Bb + swz(krow, chunk) * 16);
            }
            // A fragments: 4 m-tiles
            const int arow_off = (lane & 7) + ((lane >> 3) & 1) * 8;
            const int achunk = ks * 2 + (lane >> 4);
#pragma unroll
            for (int mi = 0; mi < 4; mi++) {
                unsigned afr[4];
                const int arow = wm * 64 + mi * 16 + arow_off;
                ldsm_x4(afr[0], afr[1], afr[2], afr[3], Ab + swz(arow, achunk) * 16);
#pragma unroll
                for (int ni = 0; ni < 4; ni++) mma16816(acc[mi][ni], afr, bfr[ni]);
            }
        }
    }

    // ---- epilogue: bias (+relu) ----
    const float* sbias = (const float*)(sm + SM_BIAS);
#pragma unroll
    for (int mi = 0; mi < 4; mi++) {
        const int r = row0 + wm * 64 + mi * 16 + (lane >> 2);
#pragma unroll
        for (int ni = 0; ni < 4; ni++) {
            const int cb = wn * 32 + ni * 8 + (lane & 3) * 2;
            const float b0 = sbias[cb], b1 = sbias[cb + 1];
            float v0 = acc[mi][ni][0] + b0, v1 = acc[mi][ni][1] + b1;
            float v2 = acc[mi][ni][2] + b0, v3 = acc[mi][ni][3] + b1;
            if (do_relu) {
                v0 = fmaxf(v0, 0.f); v1 = fmaxf(v1, 0.f);
                v2 = fmaxf(v2, 0.f); v3 = fmaxf(v3, 0.f);
            }
            if (r < M) *(float2*)(Y + (size_t)r * CH + cb) = make_float2(v0, v1);
            if (r + 8 < M) *(float2*)(Y + (size_t)(r + 8) * CH + cb) = make_float2(v2, v3);
        }
    }
}

// ---------------- edge scatter: agg[dst] += x[src], warp per edge ------------
__global__ void edge_scatter(const float* __restrict__ xsrc,
                             const int* __restrict__ esrc,
                             const int* __restrict__ edst,
                             float* __restrict__ agg, int n_edges) {
    int w = (int)((blockIdx.x * (unsigned)blockDim.x + threadIdx.x) >> 5);
    int lane = threadIdx.x & 31;
    if (w >= n_edges) return;
    int s = __ldg(&esrc[w]);
    int d = __ldg(&edst[w]);
    const float4 v = *(const float4*)(xsrc + (size_t)s * CH + lane * 4);
    float* p = agg + (size_t)d * CH + lane * 4;
    asm volatile("red.global.add.v4.f32 [%0], {%1, %2, %3, %4};"
                 :: "l"(p), "f"(v.x), "f"(v.y), "f"(v.z), "f"(v.w)
                 : "memory");
}

// ---------------- LayerNorm (node mode) + ReLU, warp per node ----------------
__global__ void ln_relu(const float* __restrict__ X, const float* __restrict__ g,
                        const float* __restrict__ b, float* __restrict__ Y, int n) {
    int w = (int)((blockIdx.x * (unsigned)blockDim.x + threadIdx.x) >> 5);
    int lane = threadIdx.x & 31;
    if (w >= n) return;
    const float4 v = *(const float4*)(X + (size_t)w * CH + lane * 4);
    float s = v.x + v.y + v.z + v.w;
#pragma unroll
    for (int o = 16; o > 0; o >>= 1) s += __shfl_xor_sync(0xffffffffu, s, o);
    float m = s * (1.0f / CH);
    float dx0 = v.x - m, dx1 = v.y - m, dx2 = v.z - m, dx3 = v.w - m;
    float ss = dx0 * dx0 + dx1 * dx1 + dx2 * dx2 + dx3 * dx3;
#pragma unroll
    for (int o = 16; o > 0; o >>= 1) ss += __shfl_xor_sync(0xffffffffu, ss, o);
    float inv = rsqrtf(ss * (1.0f / CH) + 1e-5f);
    const float4 gv = *(const float4*)(g + lane * 4);
    const float4 bv = *(const float4*)(b + lane * 4);
    float4 o4;
    o4.x = fmaxf(dx0 * inv * gv.x + bv.x, 0.0f);
    o4.y = fmaxf(dx1 * inv * gv.y + bv.y, 0.0f);
    o4.z = fmaxf(dx2 * inv * gv.z + bv.z, 0.0f);
    o4.w = fmaxf(dx3 * inv * gv.w + bv.w, 0.0f);
    *(float4*)(Y + (size_t)w * CH + lane * 4) = o4;
}

// ---------------- orchestration ---------------------------------------------
extern "C" void kernel_launch(void* const* d_in, const int* in_sizes, int n_in,
                              void* d_out, int out_size) {
    const float* x_user = (const float*)d_in[0];
    const float* x_item = (const float*)d_in[1];
    const float* W_init = (const float*)d_in[2];
    const float* b_init = (const float*)d_in[3];
    const float* mlp_W  = (const float*)d_in[4];
    const float* mlp_b  = (const float*)d_in[5];
    const float* eps    = (const float*)d_in[6];
    const float* ln_g   = (const float*)d_in[7];
    const float* ln_b   = (const float*)d_in[8];
    const int* edge_ui  = (const int*)d_in[9];
    const int* edge_iu  = (const int*)d_in[10];

    float *xu, *xi, *au, *ai, *t1u, *t2u, *t1i, *t2i;
    unsigned *Wh, *Wl;
    cudaGetSymbolAddress((void**)&xu, g_xu);
    cudaGetSymbolAddress((void**)&xi, g_xi);
    cudaGetSymbolAddress((void**)&au, g_agg_u);
    cudaGetSymbolAddress((void**)&ai, g_agg_i);
    cudaGetSymbolAddress((void**)&t1u, g_t1u);
    cudaGetSymbolAddress((void**)&t2u, g_t2u);
    cudaGetSymbolAddress((void**)&t1i, g_t1i);
    cudaGetSymbolAddress((void**)&t2i, g_t2i);
    cudaGetSymbolAddress((void**)&Wh, g_W_hi);
    cudaGetSymbolAddress((void**)&Wl, g_W_lo);

    cudaFuncSetAttribute(mma_gemm, cudaFuncAttributeMaxDynamicSharedMemorySize, SM_TOT);

    const int eblk = (NE * 32 + 255) / 256;
    const int lnu = (NU + 7) / 8;
    const int lni = (NI + 7) / 8;

    // split weights once (slots: 0=init-user, 1=init-item, 2.. = mlp in layout order)
    convW<<<10, 256>>>(W_init, mlp_W, Wh, Wl);

    // init projections (no relu)
    mma_gemm<<<TU, 256, SM_TOT>>>(x_user, nullptr, nullptr, Wh, Wl, b_init, xu, NU, 0);
    mma_gemm<<<TI, 256, SM_TOT>>>(x_item, nullptr, nullptr, Wh + 8192, Wl + 8192,
                                  b_init + CH, xi, NI, 0);

    for (int l = 0; l < NLAY; l++) {
        cudaMemsetAsync(ai, 0, (size_t)NI * CH * sizeof(float), 0);
        cudaMemsetAsync(au, 0, (size_t)NU * CH * sizeof(float), 0);
        edge_scatter<<<eblk, 256>>>(xu, edge_ui, edge_ui + NE, ai, NE);  // user->item
        edge_scatter<<<eblk, 256>>>(xi, edge_iu, edge_iu + NE, au, NE);  // item->user

        // items (edge type 0)
        {
            int s0 = 2 + (l * 2 + 0) * 2, s1 = s0 + 1;
            const float* B0 = mlp_b + (size_t)((l * 2 + 0) * 2 + 0) * CH;
            const float* B1 = mlp_b + (size_t)((l * 2 + 0) * 2 + 1) * CH;
            mma_gemm<<<TI, 256, SM_TOT>>>(xi, ai, eps + l * 2 + 0,
                                          Wh + (size_t)s0 * 8192, Wl + (size_t)s0 * 8192,
                                          B0, t1i, NI, 1);
            mma_gemm<<<TI, 256, SM_TOT>>>(t1i, nullptr, nullptr,
                                          Wh + (size_t)s1 * 8192, Wl + (size_t)s1 * 8192,
                                          B1, t2i, NI, 1);
        }
        // users (edge type 1)
        {
            int s0 = 2 + (l * 2 + 1) * 2, s1 = s0 + 1;
            const float* B0 = mlp_b + (size_t)((l * 2 + 1) * 2 + 0) * CH;
            const float* B1 = mlp_b + (size_t)((l * 2 + 1) * 2 + 1) * CH;
            mma_gemm<<<TU, 256, SM_TOT>>>(xu, au, eps + l * 2 + 1,
                                          Wh + (size_t)s0 * 8192, Wl + (size_t)s0 * 8192,
                                          B0, t1u, NU, 1);
            mma_gemm<<<TU, 256, SM_TOT>>>(t1u, nullptr, nullptr,
                                          Wh + (size_t)s1 * 8192, Wl + (size_t)s1 * 8192,
                                          B1, t2u, NU, 1);
        }

        float* ou = (l == NLAY - 1) ? (float*)d_out : xu;
        float* oi = (l == NLAY - 1) ? (float*)d_out + (size_t)NU * CH : xi;
        ln_relu<<<lnu, 256>>>(t2u, ln_g + (l * 2 + 0) * CH, ln_b + (l * 2 + 0) * CH, ou, NU);
        ln_relu<<<lni, 256>>>(t2i, ln_g + (l * 2 + 1) * CH, ln_b + (l * 2 + 1) * CH, oi, NI);
    }
}

// round 12
// speedup vs baseline: 1.6801x; 1.0463x over previous
#include <cuda_runtime.h>
#include <cstdint>

#define NU 100000
#define NI 50000
#define CH 128
#define NE 600000
#define NLAY 2
#define TU ((NU + 127) / 128)
#define TI ((NI + 127) / 128)

// ---------------- scratch (device globals; no allocation allowed) ------------
__device__ float g_xu[NU * CH];
__device__ float g_xi[NI * CH];
__device__ float g_agg_u[NU * CH];   // combined (1+eps)*x + agg
__device__ float g_agg_i[NI * CH];
__device__ float g_t1u[NU * CH];
__device__ float g_t2u[NU * CH];
__device__ float g_t1i[NI * CH];
__device__ float g_t2i[NI * CH];
// weights, bf16 hi/lo split
__device__ unsigned g_W_hi[10 * 8192];
__device__ unsigned g_W_lo[10 * 8192];
// CSR structures (rebuilt every launch; deterministic)
__device__ int g_rp_u[NU + 1];
__device__ int g_rp_i[NI + 1];
__device__ int g_cnt_u[NU];          // histogram, then reused as fill cursor
__device__ int g_cnt_i[NI];
__device__ int g_col_u[NE];          // src item per (dst-user-sorted) edge
__device__ int g_col_i[NE];          // src user per (dst-item-sorted) edge

// ---------------- bf16 split helpers -----------------------------------------
__device__ __forceinline__ unsigned packbf(float a, float b) {  // lo=a, hi=b
    unsigned r;
    asm("cvt.rn.satfinite.bf16x2.f32 %0, %1, %2;" : "=r"(r) : "f"(b), "f"(a));
    return r;
}
__device__ __forceinline__ float bflo(unsigned p) { return __uint_as_float(p << 16); }
__device__ __forceinline__ float bfhi(unsigned p) { return __uint_as_float(p & 0xffff0000u); }

__device__ __forceinline__ unsigned smem_u32(const void* p) {
    unsigned a;
    asm("{ .reg .u64 t; cvta.to.shared.u64 t, %1; cvt.u32.u64 %0, t; }"
        : "=r"(a) : "l"(p));
    return a;
}
__device__ __forceinline__ void ldsm_x4(unsigned& r0, unsigned& r1, unsigned& r2,
                                        unsigned& r3, unsigned addr) {
    asm volatile("ldmatrix.sync.aligned.m8n8.x4.shared.b16 {%0,%1,%2,%3}, [%4];"
                 : "=r"(r0), "=r"(r1), "=r"(r2), "=r"(r3) : "r"(addr));
}
__device__ __forceinline__ void ldsm_x2t(unsigned& r0, unsigned& r1, unsigned addr) {
    asm volatile("ldmatrix.sync.aligned.m8n8.x2.trans.shared.b16 {%0,%1}, [%2];"
                 : "=r"(r0), "=r"(r1) : "r"(addr));
}
__device__ __forceinline__ void mma16816(float* d, const unsigned* a, const unsigned* b) {
    asm volatile(
        "mma.sync.aligned.m16n8k16.row.col.f32.bf16.bf16.f32 "
        "{%0,%1,%2,%3}, {%4,%5,%6,%7}, {%8,%9}, {%0,%1,%2,%3};"
        : "+f"(d[0]), "+f"(d[1]), "+f"(d[2]), "+f"(d[3])
        : "r"(a[0]), "r"(a[1]), "r"(a[2]), "r"(a[3]), "r"(b[0]), "r"(b[1]));
}

// swizzled chunk index (16B units) for a 128x128 bf16 tile: row r, 16B-chunk c
__device__ __forceinline__ int swz(int r, int c) { return r * 16 + (c ^ (r & 7)); }

// ---------------- convW: bf16 hi/lo split of 10 weight matrices --------------
__global__ void convW(const float* __restrict__ W_init, const float* __restrict__ mlp_W,
                      unsigned* __restrict__ Whi, unsigned* __restrict__ Wlo) {
    const int m = blockIdx.x;  // 0..9
    const float* W = (m < 2) ? (W_init + (size_t)m * CH * CH)
                             : (mlp_W + (size_t)(m - 2) * CH * CH);
    for (int t = threadIdx.x; t < 8192; t += blockDim.x) {
        float w0 = W[2 * t], w1 = W[2 * t + 1];
        unsigned hi = packbf(w0, w1);
        unsigned lo = packbf(w0 - bflo(hi), w1 - bfhi(hi));
        Whi[m * 8192 + t] = hi;
        Wlo[m * 8192 + t] = lo;
    }
}

// ---------------- CSR build ----------------------------------------------------
__global__ void hist2(const int* __restrict__ eui, const int* __restrict__ eiu,
                      int* __restrict__ cnt_i, int* __restrict__ cnt_u) {
    int e = blockIdx.x * blockDim.x + threadIdx.x;
    if (e >= NE) return;
    atomicAdd(&cnt_i[__ldg(&eui[NE + e])], 1);
    atomicAdd(&cnt_u[__ldg(&eiu[NE + e])], 1);
}

// exclusive scan; also overwrites cnt with the running offsets (fill cursor)
__global__ __launch_bounds__(1024) void scan2(int* __restrict__ cnt_i, int* __restrict__ rp_i,
                                              int* __restrict__ cnt_u, int* __restrict__ rp_u) {
    __shared__ int part[1024];
    const int n = blockIdx.x ? NU : NI;
    int* cnt = blockIdx.x ? cnt_u : cnt_i;
    int* rp = blockIdx.x ? rp_u : rp_i;
    const int tid = threadIdx.x;
    const int chunk = (n + 1023) / 1024;
    const int lo = tid * chunk;
    const int hi = (lo + chunk < n) ? lo + chunk : n;
    int s = 0;
    for (int i = lo; i < hi; i++) s += cnt[i];
    part[tid] = s;
    __syncthreads();
    for (int off = 1; off < 1024; off <<= 1) {
        int v = (tid >= off) ? part[tid - off] : 0;
        __syncthreads();
        part[tid] += v;
        __syncthreads();
    }
    int run = tid ? part[tid - 1] : 0;
    for (int i = lo; i < hi; i++) {
        int c = cnt[i];
        rp[i] = run;
        cnt[i] = run;   // becomes cursor for fill
        run += c;
    }
    if (tid == 1023) rp[n] = run;
}

__global__ void fill2(const int* __restrict__ eui, const int* __restrict__ eiu,
                      int* __restrict__ cur_i, int* __restrict__ cur_u,
                      int* __restrict__ col_i, int* __restrict__ col_u) {
    int e = blockIdx.x * blockDim.x + threadIdx.x;
    if (e >= NE) return;
    int di = __ldg(&eui[NE + e]);
    col_i[atomicAdd(&cur_i[di], 1)] = __ldg(&eui[e]);
    int du = __ldg(&eiu[NE + e]);
    col_u[atomicAdd(&cur_u[du], 1)] = __ldg(&eiu[e]);
}

// ---------------- pull aggregation: out[d] = (1+eps)*XS[d] + sum XG[nbr] -----
__global__ void pull_agg(const int* __restrict__ rp, const int* __restrict__ col,
                         const float* __restrict__ XG, const float* __restrict__ XS,
                         const float* __restrict__ epsp, float* __restrict__ out, int n) {
    int w = (int)((blockIdx.x * (unsigned)blockDim.x + threadIdx.x) >> 5);
    int lane = threadIdx.x & 31;
    if (w >= n) return;
    const float alpha = 1.0f + __ldg(epsp);
    const float4 sv = *(const float4*)(XS + (size_t)w * CH + lane * 4);
    float ax = alpha * sv.x, ay = alpha * sv.y, az = alpha * sv.z, aw = alpha * sv.w;
    const int beg = __ldg(&rp[w]);
    const int end = __ldg(&rp[w + 1]);
    int j = beg;
    for (; j + 4 <= end; j += 4) {
        int s0 = __ldg(&col[j]), s1 = __ldg(&col[j + 1]);
        int s2 = __ldg(&col[j + 2]), s3 = __ldg(&col[j + 3]);
        const float4 v0 = *(const float4*)(XG + (size_t)s0 * CH + lane * 4);
        const float4 v1 = *(const float4*)(XG + (size_t)s1 * CH + lane * 4);
        const float4 v2 = *(const float4*)(XG + (size_t)s2 * CH + lane * 4);
        const float4 v3 = *(const float4*)(XG + (size_t)s3 * CH + lane * 4);
        ax += (v0.x + v1.x) + (v2.x + v3.x);
        ay += (v0.y + v1.y) + (v2.y + v3.y);
        az += (v0.z + v1.z) + (v2.z + v3.z);
        aw += (v0.w + v1.w) + (v2.w + v3.w);
    }
    for (; j < end; j++) {
        int s = __ldg(&col[j]);
        const float4 v = *(const float4*)(XG + (size_t)s * CH + lane * 4);
        ax += v.x; ay += v.y; az += v.z; aw += v.w;
    }
    *(float4*)(out + (size_t)w * CH + lane * 4) = make_float4(ax, ay, az, aw);
}

// ---------------- tensor-core GEMM: Y = act((alpha*X+AGG) @ W + bias) --------
#define SMW_HI 0
#define SMW_LO 32768
#define SMA_HI 65536
#define SMA_LO 98304
#define SM_BIAS 131072
#define SM_TOT (131072 + 512)

__global__ __launch_bounds__(256) void mma_gemm(
    const float* __restrict__ X, const float* __restrict__ AGG,
    const float* __restrict__ epsp,
    const unsigned* __restrict__ Whi, const unsigned* __restrict__ Wlo,
    const float* __restrict__ bias, float* __restrict__ Y, int M, int do_relu) {
    extern __shared__ char sm[];
    const int tid = threadIdx.x, wid = tid >> 5, lane = tid & 31;
    const int row0 = blockIdx.x * 128;
    const float alpha = epsp ? (1.0f + __ldg(epsp)) : 1.0f;

    // ---- load W hi/lo into swizzled SMEM ----
    {
        const uint4* gh = (const uint4*)Whi;
        const uint4* gl = (const uint4*)Wlo;
        uint4* sh = (uint4*)(sm + SMW_HI);
        uint4* sl = (uint4*)(sm + SMW_LO);
#pragma unroll
        for (int q = 0; q < 8; q++) {
            int c = tid + 256 * q;
            int r = c >> 4, ch = c & 15;
            int d = swz(r, ch);
            sh[d] = gh[c];
            sl[d] = gl[c];
        }
    }
    // ---- load A (fp32, optional fused alpha*x+agg) -> bf16 hi/lo swizzled ----
    {
        uint4* sh = (uint4*)(sm + SMA_HI);
        uint4* sl = (uint4*)(sm + SMA_LO);
#pragma unroll
        for (int q = 0; q < 8; q++) {
            int c = tid + 256 * q;
            int r = c >> 4, ch = c & 15;
            int grow = row0 + r;
            float v[8];
#pragma unroll
            for (int j = 0; j < 8; j++) v[j] = 0.0f;
            if (grow < M) {
                const float4* p = (const float4*)(X + (size_t)grow * CH + ch * 8);
                float4 v0 = p[0], v1 = p[1];
                if (AGG) {
                    const float4* g = (const float4*)(AGG + (size_t)grow * CH + ch * 8);
                    float4 g0 = g[0], g1 = g[1];
                    v0.x = fmaf(alpha, v0.x, g0.x); v0.y = fmaf(alpha, v0.y, g0.y);
                    v0.z = fmaf(alpha, v0.z, g0.z); v0.w = fmaf(alpha, v0.w, g0.w);
                    v1.x = fmaf(alpha, v1.x, g1.x); v1.y = fmaf(alpha, v1.y, g1.y);
                    v1.z = fmaf(alpha, v1.z, g1.z); v1.w = fmaf(alpha, v1.w, g1.w);
                }
                v[0] = v0.x; v[1] = v0.y; v[2] = v0.z; v[3] = v0.w;
                v[4] = v1.x; v[5] = v1.y; v[6] = v1.z; v[7] = v1.w;
            }
            unsigned hi[4], lo[4];
#pragma unroll
            for (int j = 0; j < 4; j++) {
                hi[j] = packbf(v[2 * j], v[2 * j + 1]);
                lo[j] = packbf(v[2 * j] - bflo(hi[j]), v[2 * j + 1] - bfhi(hi[j]));
            }
            int d = swz(r, ch);
            sh[d] = make_uint4(hi[0], hi[1], hi[2], hi[3]);
            sl[d] = make_uint4(lo[0], lo[1], lo[2], lo[3]);
        }
    }
    if (tid < 128) ((float*)(sm + SM_BIAS))[tid] = bias[tid];
    __syncthreads();

    const int wm = wid & 1;
    const int wn = wid >> 1;
    const unsigned base = smem_u32(sm);

    float acc[4][4][4];
#pragma unroll
    for (int mi = 0; mi < 4; mi++)
#pragma unroll
        for (int ni = 0; ni < 4; ni++)
#pragma unroll
            for (int j = 0; j < 4; j++) acc[mi][ni][j] = 0.0f;

#pragma unroll
    for (int pass = 0; pass < 3; pass++) {
        const unsigned Ab = base + ((pass == 2) ? SMA_LO : SMA_HI);
        const unsigned Bb = base + ((pass == 1) ? SMW_LO : SMW_HI);
#pragma unroll
        for (int ks = 0; ks < 8; ks++) {
            unsigned bfr[4][2];
            const int krow = ks * 16 + (lane & 15);
#pragma unroll
            for (int ni = 0; ni < 4; ni++) {
                const int chunk = wn * 4 + ni;
                ldsm_x2t(bfr[ni][0], bfr[ni][1], Bb + swz(krow, chunk) * 16);
            }
            const int arow_off = (lane & 7) + ((lane >> 3) & 1) * 8;
            const int achunk = ks * 2 + (lane >> 4);
#pragma unroll
            for (int mi = 0; mi < 4; mi++) {
                unsigned afr[4];
                const int arow = wm * 64 + mi * 16 + arow_off;
                ldsm_x4(afr[0], afr[1], afr[2], afr[3], Ab + swz(arow, achunk) * 16);
#pragma unroll
                for (int ni = 0; ni < 4; ni++) mma16816(acc[mi][ni], afr, bfr[ni]);
            }
        }
    }

    const float* sbias = (const float*)(sm + SM_BIAS);
#pragma unroll
    for (int mi = 0; mi < 4; mi++) {
        const int r = row0 + wm * 64 + mi * 16 + (lane >> 2);
#pragma unroll
        for (int ni = 0; ni < 4; ni++) {
            const int cb = wn * 32 + ni * 8 + (lane & 3) * 2;
            const float b0 = sbias[cb], b1 = sbias[cb + 1];
            float v0 = acc[mi][ni][0] + b0, v1 = acc[mi][ni][1] + b1;
            float v2 = acc[mi][ni][2] + b0, v3 = acc[mi][ni][3] + b1;
            if (do_relu) {
                v0 = fmaxf(v0, 0.f); v1 = fmaxf(v1, 0.f);
                v2 = fmaxf(v2, 0.f); v3 = fmaxf(v3, 0.f);
            }
            if (r < M) *(float2*)(Y + (size_t)r * CH + cb) = make_float2(v0, v1);
            if (r + 8 < M) *(float2*)(Y + (size_t)(r + 8) * CH + cb) = make_float2(v2, v3);
        }
    }
}

// ---------------- LayerNorm (node mode) + ReLU, warp per node ----------------
__global__ void ln_relu(const float* __restrict__ X, const float* __restrict__ g,
                        const float* __restrict__ b, float* __restrict__ Y, int n) {
    int w = (int)((blockIdx.x * (unsigned)blockDim.x + threadIdx.x) >> 5);
    int lane = threadIdx.x & 31;
    if (w >= n) return;
    const float4 v = *(const float4*)(X + (size_t)w * CH + lane * 4);
    float s = v.x + v.y + v.z + v.w;
#pragma unroll
    for (int o = 16; o > 0; o >>= 1) s += __shfl_xor_sync(0xffffffffu, s, o);
    float m = s * (1.0f / CH);
    float dx0 = v.x - m, dx1 = v.y - m, dx2 = v.z - m, dx3 = v.w - m;
    float ss = dx0 * dx0 + dx1 * dx1 + dx2 * dx2 + dx3 * dx3;
#pragma unroll
    for (int o = 16; o > 0; o >>= 1) ss += __shfl_xor_sync(0xffffffffu, ss, o);
    float inv = rsqrtf(ss * (1.0f / CH) + 1e-5f);
    const float4 gv = *(const float4*)(g + lane * 4);
    const float4 bv = *(const float4*)(b + lane * 4);
    float4 o4;
    o4.x = fmaxf(dx0 * inv * gv.x + bv.x, 0.0f);
    o4.y = fmaxf(dx1 * inv * gv.y + bv.y, 0.0f);
    o4.z = fmaxf(dx2 * inv * gv.z + bv.z, 0.0f);
    o4.w = fmaxf(dx3 * inv * gv.w + bv.w, 0.0f);
    *(float4*)(Y + (size_t)w * CH + lane * 4) = o4;
}

// ---------------- orchestration ---------------------------------------------
extern "C" void kernel_launch(void* const* d_in, const int* in_sizes, int n_in,
                              void* d_out, int out_size) {
    const float* x_user = (const float*)d_in[0];
    const float* x_item = (const float*)d_in[1];
    const float* W_init = (const float*)d_in[2];
    const float* b_init = (const float*)d_in[3];
    const float* mlp_W  = (const float*)d_in[4];
    const float* mlp_b  = (const float*)d_in[5];
    const float* eps    = (const float*)d_in[6];
    const float* ln_g   = (const float*)d_in[7];
    const float* ln_b   = (const float*)d_in[8];
    const int* edge_ui  = (const int*)d_in[9];
    const int* edge_iu  = (const int*)d_in[10];

    float *xu, *xi, *au, *ai, *t1u, *t2u, *t1i, *t2i;
    unsigned *Wh, *Wl;
    int *rp_u, *rp_i, *cnt_u, *cnt_i, *col_u, *col_i;
    cudaGetSymbolAddress((void**)&xu, g_xu);
    cudaGetSymbolAddress((void**)&xi, g_xi);
    cudaGetSymbolAddress((void**)&au, g_agg_u);
    cudaGetSymbolAddress((void**)&ai, g_agg_i);
    cudaGetSymbolAddress((void**)&t1u, g_t1u);
    cudaGetSymbolAddress((void**)&t2u, g_t2u);
    cudaGetSymbolAddress((void**)&t1i, g_t1i);
    cudaGetSymbolAddress((void**)&t2i, g_t2i);
    cudaGetSymbolAddress((void**)&Wh, g_W_hi);
    cudaGetSymbolAddress((void**)&Wl, g_W_lo);
    cudaGetSymbolAddress((void**)&rp_u, g_rp_u);
    cudaGetSymbolAddress((void**)&rp_i, g_rp_i);
    cudaGetSymbolAddress((void**)&cnt_u, g_cnt_u);
    cudaGetSymbolAddress((void**)&cnt_i, g_cnt_i);
    cudaGetSymbolAddress((void**)&col_u, g_col_u);
    cudaGetSymbolAddress((void**)&col_i, g_col_i);

    cudaFuncSetAttribute(mma_gemm, cudaFuncAttributeMaxDynamicSharedMemorySize, SM_TOT);

    const int eblk = (NE + 255) / 256;
    const int lnu = (NU + 7) / 8;
    const int lni = (NI + 7) / 8;
    const int plu = (NU * 32 + 255) / 256;
    const int pli = (NI * 32 + 255) / 256;

    // ---- CSR build (both directions) ----
    cudaMemsetAsync(cnt_u, 0, NU * sizeof(int), 0);
    cudaMemsetAsync(cnt_i, 0, NI * sizeof(int), 0);
    hist2<<<eblk, 256>>>(edge_ui, edge_iu, cnt_i, cnt_u);
    scan2<<<2, 1024>>>(cnt_i, rp_i, cnt_u, rp_u);
    fill2<<<eblk, 256>>>(edge_ui, edge_iu, cnt_i, cnt_u, col_i, col_u);

    // ---- weights: bf16 hi/lo split once ----
    convW<<<10, 256>>>(W_init, mlp_W, Wh, Wl);

    // ---- init projections (no relu) ----
    mma_gemm<<<TU, 256, SM_TOT>>>(x_user, nullptr, nullptr, Wh, Wl, b_init, xu, NU, 0);
    mma_gemm<<<TI, 256, SM_TOT>>>(x_item, nullptr, nullptr, Wh + 8192, Wl + 8192,
                                  b_init + CH, xi, NI, 0);

    for (int l = 0; l < NLAY; l++) {
        // combined (1+eps)*self + neighbor sum, via CSR pull (no atomics, no memset)
        pull_agg<<<pli, 256>>>(rp_i, col_i, xu, xi, eps + l * 2 + 0, ai, NI);
        pull_agg<<<plu, 256>>>(rp_u, col_u, xi, xu, eps + l * 2 + 1, au, NU);

        // items (edge type 0)
        {
            int s0 = 2 + (l * 2 + 0) * 2, s1 = s0 + 1;
            const float* B0 = mlp_b + (size_t)((l * 2 + 0) * 2 + 0) * CH;
            const float* B1 = mlp_b + (size_t)((l * 2 + 0) * 2 + 1) * CH;
            mma_gemm<<<TI, 256, SM_TOT>>>(ai, nullptr, nullptr,
                                          Wh + (size_t)s0 * 8192, Wl + (size_t)s0 * 8192,
                                          B0, t1i, NI, 1);
            mma_gemm<<<TI, 256, SM_TOT>>>(t1i, nullptr, nullptr,
                                          Wh + (size_t)s1 * 8192, Wl + (size_t)s1 * 8192,
                                          B1, t2i, NI, 1);
        }
        // users (edge type 1)
        {
            int s0 = 2 + (l * 2 + 1) * 2, s1 = s0 + 1;
            const float* B0 = mlp_b + (size_t)((l * 2 + 1) * 2 + 0) * CH;
            const float* B1 = mlp_b + (size_t)((l * 2 + 1) * 2 + 1) * CH;
            mma_gemm<<<TU, 256, SM_TOT>>>(au, nullptr, nullptr,
                                          Wh + (size_t)s0 * 8192, Wl + (size_t)s0 * 8192,
                                          B0, t1u, NU, 1);
            mma_gemm<<<TU, 256, SM_TOT>>>(t1u, nullptr, nullptr,
                                          Wh + (size_t)s1 * 8192, Wl + (size_t)s1 * 8192,
                                          B1, t2u, NU, 1);
        }

        float* ou = (l == NLAY - 1) ? (float*)d_out : xu;
        float* oi = (l == NLAY - 1) ? (float*)d_out + (size_t)NU * CH : xi;
        ln_relu<<<lnu, 256>>>(t2u, ln_g + (l * 2 + 0) * CH, ln_b + (l * 2 + 0) * CH, ou, NU);
        ln_relu<<<lni, 256>>>(t2i, ln_g + (l * 2 + 1) * CH, ln_b + (l * 2 + 1) * CH, oi, NI);
    }
}

// round 13
// speedup vs baseline: 1.9013x; 1.1316x over previous
#include <cuda_runtime.h>
#include <cstdint>

#define NU 100000
#define NI 50000
#define CH 128
#define NE 600000
#define NLAY 2
#define TU ((NU + 127) / 128)
#define TI ((NI + 127) / 128)

// ---------------- scratch (device globals; no allocation allowed) ------------
__device__ float g_xu[NU * CH];
__device__ float g_xi[NI * CH];
__device__ float g_agg_u[NU * CH];   // combined (1+eps)*x + neighbor sum
__device__ float g_agg_i[NI * CH];
// weights, bf16 hi/lo split
__device__ unsigned g_W_hi[10 * 8192];
__device__ unsigned g_W_lo[10 * 8192];
// CSR structures
__device__ int g_rp_u[NU + 1];
__device__ int g_rp_i[NI + 1];
__device__ int g_cnt_u[NU];
__device__ int g_cnt_i[NI];
__device__ int g_col_u[NE];
__device__ int g_col_i[NE];

// ---------------- bf16 split helpers -----------------------------------------
__device__ __forceinline__ unsigned packbf(float a, float b) {  // lo=a, hi=b
    unsigned r;
    asm("cvt.rn.satfinite.bf16x2.f32 %0, %1, %2;" : "=r"(r) : "f"(b), "f"(a));
    return r;
}
__device__ __forceinline__ float bflo(unsigned p) { return __uint_as_float(p << 16); }
__device__ __forceinline__ float bfhi(unsigned p) { return __uint_as_float(p & 0xffff0000u); }

__device__ __forceinline__ unsigned smem_u32(const void* p) {
    unsigned a;
    asm("{ .reg .u64 t; cvta.to.shared.u64 t, %1; cvt.u32.u64 %0, t; }"
        : "=r"(a) : "l"(p));
    return a;
}
__device__ __forceinline__ void ldsm_x4(unsigned& r0, unsigned& r1, unsigned& r2,
                                        unsigned& r3, unsigned addr) {
    asm volatile("ldmatrix.sync.aligned.m8n8.x4.shared.b16 {%0,%1,%2,%3}, [%4];"
                 : "=r"(r0), "=r"(r1), "=r"(r2), "=r"(r3) : "r"(addr));
}
__device__ __forceinline__ void ldsm_x2t(unsigned& r0, unsigned& r1, unsigned addr) {
    asm volatile("ldmatrix.sync.aligned.m8n8.x2.trans.shared.b16 {%0,%1}, [%2];"
                 : "=r"(r0), "=r"(r1) : "r"(addr));
}
__device__ __forceinline__ void mma16816(float* d, const unsigned* a, const unsigned* b) {
    asm volatile(
        "mma.sync.aligned.m16n8k16.row.col.f32.bf16.bf16.f32 "
        "{%0,%1,%2,%3}, {%4,%5,%6,%7}, {%8,%9}, {%0,%1,%2,%3};"
        : "+f"(d[0]), "+f"(d[1]), "+f"(d[2]), "+f"(d[3])
        : "r"(a[0]), "r"(a[1]), "r"(a[2]), "r"(a[3]), "r"(b[0]), "r"(b[1]));
}

// swizzled chunk index (16B units) for a 128x128 bf16 tile: row r, 16B-chunk c
__device__ __forceinline__ int swz(int r, int c) { return r * 16 + (c ^ (r & 7)); }

// ---------------- shared GEMM core: acc = A_tile @ W_tile (3-term split) -----
__device__ __forceinline__ void do_gemm(const unsigned base, int aHi, int aLo,
                                        int wHi, int wLo, int wm, int wn, int lane,
                                        float acc[4][4][4]) {
#pragma unroll
    for (int mi = 0; mi < 4; mi++)
#pragma unroll
        for (int ni = 0; ni < 4; ni++)
#pragma unroll
            for (int j = 0; j < 4; j++) acc[mi][ni][j] = 0.0f;
#pragma unroll
    for (int pass = 0; pass < 3; pass++) {
        const unsigned Ab = base + ((pass == 2) ? aLo : aHi);
        const unsigned Bb = base + ((pass == 1) ? wLo : wHi);
#pragma unroll
        for (int ks = 0; ks < 8; ks++) {
            unsigned bfr[4][2];
            const int krow = ks * 16 + (lane & 15);
#pragma unroll
            for (int ni = 0; ni < 4; ni++)
                ldsm_x2t(bfr[ni][0], bfr[ni][1], Bb + swz(krow, wn * 4 + ni) * 16);
            const int arow_off = (lane & 7) + ((lane >> 3) & 1) * 8;
            const int achunk = ks * 2 + (lane >> 4);
#pragma unroll
            for (int mi = 0; mi < 4; mi++) {
                unsigned afr[4];
                const int arow = wm * 64 + mi * 16 + arow_off;
                ldsm_x4(afr[0], afr[1], afr[2], afr[3], Ab + swz(arow, achunk) * 16);
#pragma unroll
                for (int ni = 0; ni < 4; ni++) mma16816(acc[mi][ni], afr, bfr[ni]);
            }
        }
    }
}

// load a 32KB bf16 image (global, linear chunks) into swizzled SMEM
__device__ __forceinline__ void load_w32k(const unsigned* g, char* s, int tid) {
    const uint4* gv = (const uint4*)g;
    uint4* sv = (uint4*)s;
#pragma unroll
    for (int q = 0; q < 8; q++) {
        int c = tid + 256 * q;
        sv[swz(c >> 4, c & 15)] = gv[c];
    }
}

// load fp32 A rows -> bf16 hi/lo swizzled SMEM (zero-fill rows >= M)
__device__ __forceinline__ void load_a(const float* X, int row0, int M,
                                       char* shp, char* slp, int tid) {
    uint4* sh = (uint4*)shp;
    uint4* sl = (uint4*)slp;
#pragma unroll
    for (int q = 0; q < 8; q++) {
        int c = tid + 256 * q;
        int r = c >> 4, ch = c & 15;
        int grow = row0 + r;
        float v[8];
#pragma unroll
        for (int j = 0; j < 8; j++) v[j] = 0.0f;
        if (grow < M) {
            const float4* p = (const float4*)(X + (size_t)grow * CH + ch * 8);
            float4 v0 = p[0], v1 = p[1];
            v[0] = v0.x; v[1] = v0.y; v[2] = v0.z; v[3] = v0.w;
            v[4] = v1.x; v[5] = v1.y; v[6] = v1.z; v[7] = v1.w;
        }
        unsigned hi[4], lo[4];
#pragma unroll
        for (int j = 0; j < 4; j++) {
            hi[j] = packbf(v[2 * j], v[2 * j + 1]);
            lo[j] = packbf(v[2 * j] - bflo(hi[j]), v[2 * j + 1] - bfhi(hi[j]));
        }
        int d = swz(r, ch);
        sh[d] = make_uint4(hi[0], hi[1], hi[2], hi[3]);
        sl[d] = make_uint4(lo[0], lo[1], lo[2], lo[3]);
    }
}

// ---------------- convW: bf16 hi/lo split of 10 weight matrices --------------
__global__ void convW(const float* __restrict__ W_init, const float* __restrict__ mlp_W,
                      unsigned* __restrict__ Whi, unsigned* __restrict__ Wlo) {
    const int m = blockIdx.x;
    const float* W = (m < 2) ? (W_init + (size_t)m * CH * CH)
                             : (mlp_W + (size_t)(m - 2) * CH * CH);
    for (int t = threadIdx.x; t < 8192; t += blockDim.x) {
        float w0 = W[2 * t], w1 = W[2 * t + 1];
        unsigned hi = packbf(w0, w1);
        unsigned lo = packbf(w0 - bflo(hi), w1 - bfhi(hi));
        Whi[m * 8192 + t] = hi;
        Wlo[m * 8192 + t] = lo;
    }
}

// ---------------- CSR build ---------------------------------------------------
__global__ void hist2(const int* __restrict__ eui, const int* __restrict__ eiu,
                      int* __restrict__ cnt_i, int* __restrict__ cnt_u) {
    int e = blockIdx.x * blockDim.x + threadIdx.x;
    if (e >= NE) return;
    atomicAdd(&cnt_i[__ldg(&eui[NE + e])], 1);
    atomicAdd(&cnt_u[__ldg(&eiu[NE + e])], 1);
}

__global__ __launch_bounds__(1024) void scan2(int* __restrict__ cnt_i, int* __restrict__ rp_i,
                                              int* __restrict__ cnt_u, int* __restrict__ rp_u) {
    __shared__ int part[1024];
    const int n = blockIdx.x ? NU : NI;
    int* cnt = blockIdx.x ? cnt_u : cnt_i;
    int* rp = blockIdx.x ? rp_u : rp_i;
    const int tid = threadIdx.x;
    const int chunk = (n + 1023) / 1024;
    const int lo = tid * chunk;
    const int hi = (lo + chunk < n) ? lo + chunk : n;
    int s = 0;
    for (int i = lo; i < hi; i++) s += cnt[i];
    part[tid] = s;
    __syncthreads();
    for (int off = 1; off < 1024; off <<= 1) {
        int v = (tid >= off) ? part[tid - off] : 0;
        __syncthreads();
        part[tid] += v;
        __syncthreads();
    }
    int run = tid ? part[tid - 1] : 0;
    for (int i = lo; i < hi; i++) {
        int c = cnt[i];
        rp[i] = run;
        cnt[i] = run;
        run += c;
    }
    if (tid == 1023) rp[n] = run;
}

__global__ void fill2(const int* __restrict__ eui, const int* __restrict__ eiu,
                      int* __restrict__ cur_i, int* __restrict__ cur_u,
                      int* __restrict__ col_i, int* __restrict__ col_u) {
    int e = blockIdx.x * blockDim.x + threadIdx.x;
    if (e >= NE) return;
    int di = __ldg(&eui[NE + e]);
    col_i[atomicAdd(&cur_i[di], 1)] = __ldg(&eui[e]);
    int du = __ldg(&eiu[NE + e]);
    col_u[atomicAdd(&cur_u[du], 1)] = __ldg(&eiu[e]);
}

// ---------------- merged pull: both directions in one launch ------------------
__global__ void pull_all(const int* __restrict__ rp_i, const int* __restrict__ col_i,
                         const int* __restrict__ rp_u, const int* __restrict__ col_u,
                         const float* __restrict__ xu, const float* __restrict__ xi,
                         const float* __restrict__ eps2,
                         float* __restrict__ ai, float* __restrict__ au) {
    int w = (int)((blockIdx.x * (unsigned)blockDim.x + threadIdx.x) >> 5);
    int lane = threadIdx.x & 31;
    const int* rp;
    const int* col;
    const float* XG;
    const float* XS;
    float* out;
    float alpha;
    int idx;
    if (w < NI) {
        idx = w; rp = rp_i; col = col_i; XG = xu; XS = xi; out = ai;
        alpha = 1.0f + __ldg(&eps2[0]);
    } else {
        idx = w - NI;
        if (idx >= NU) return;
        rp = rp_u; col = col_u; XG = xi; XS = xu; out = au;
        alpha = 1.0f + __ldg(&eps2[1]);
    }
    const float4 sv = *(const float4*)(XS + (size_t)idx * CH + lane * 4);
    float ax = alpha * sv.x, ay = alpha * sv.y, az = alpha * sv.z, aw = alpha * sv.w;
    const int beg = __ldg(&rp[idx]);
    const int end = __ldg(&rp[idx + 1]);
    int j = beg;
    for (; j + 4 <= end; j += 4) {
        int s0 = __ldg(&col[j]), s1 = __ldg(&col[j + 1]);
        int s2 = __ldg(&col[j + 2]), s3 = __ldg(&col[j + 3]);
        const float4 v0 = *(const float4*)(XG + (size_t)s0 * CH + lane * 4);
        const float4 v1 = *(const float4*)(XG + (size_t)s1 * CH + lane * 4);
        const float4 v2 = *(const float4*)(XG + (size_t)s2 * CH + lane * 4);
        const float4 v3 = *(const float4*)(XG + (size_t)s3 * CH + lane * 4);
        ax += (v0.x + v1.x) + (v2.x + v3.x);
        ay += (v0.y + v1.y) + (v2.y + v3.y);
        az += (v0.z + v1.z) + (v2.z + v3.z);
        aw += (v0.w + v1.w) + (v2.w + v3.w);
    }
    for (; j < end; j++) {
        int s = __ldg(&col[j]);
        const float4 v = *(const float4*)(XG + (size_t)s * CH + lane * 4);
        ax += v.x; ay += v.y; az += v.z; aw += v.w;
    }
    *(float4*)(out + (size_t)idx * CH + lane * 4) = make_float4(ax, ay, az, aw);
}

// ---------------- merged init projection GEMM (user + item in one grid) ------
#define IG_WHI 0
#define IG_WLO 32768
#define IG_AHI 65536
#define IG_ALO 98304
#define IG_BIAS 131072
#define IG_TOT (131072 + 512)

__global__ __launch_bounds__(256) void init_gemm(
    const float* __restrict__ x_user, const float* __restrict__ x_item,
    const unsigned* __restrict__ Whi, const unsigned* __restrict__ Wlo,
    const float* __restrict__ b_init, float* __restrict__ xu, float* __restrict__ xi) {
    extern __shared__ char sm[];
    const int tid = threadIdx.x, wid = tid >> 5, lane = tid & 31;
    const bool user = blockIdx.x < TU;
    const int tile = user ? blockIdx.x : blockIdx.x - TU;
    const int M = user ? NU : NI;
    const int row0 = tile * 128;
    const float* X = user ? x_user : x_item;
    const int slot = user ? 0 : 1;
    const float* bias = b_init + (user ? 0 : CH);
    float* Y = user ? xu : xi;

    load_w32k(Whi + slot * 8192, sm + IG_WHI, tid);
    load_w32k(Wlo + slot * 8192, sm + IG_WLO, tid);
    load_a(X, row0, M, sm + IG_AHI, sm + IG_ALO, tid);
    if (tid < 128) ((float*)(sm + IG_BIAS))[tid] = bias[tid];
    __syncthreads();

    const int wm = wid & 1, wn = wid >> 1;
    const unsigned base = smem_u32(sm);
    float acc[4][4][4];
    do_gemm(base, IG_AHI, IG_ALO, IG_WHI, IG_WLO, wm, wn, lane, acc);

    const float* sbias = (const float*)(sm + IG_BIAS);
#pragma unroll
    for (int mi = 0; mi < 4; mi++) {
        const int r = row0 + wm * 64 + mi * 16 + (lane >> 2);
#pragma unroll
        for (int ni = 0; ni < 4; ni++) {
            const int cb = wn * 32 + ni * 8 + (lane & 3) * 2;
            const float b0 = sbias[cb], b1 = sbias[cb + 1];
            if (r < M)
                *(float2*)(Y + (size_t)r * CH + cb) =
                    make_float2(acc[mi][ni][0] + b0, acc[mi][ni][1] + b1);
            if (r + 8 < M)
                *(float2*)(Y + (size_t)(r + 8) * CH + cb) =
                    make_float2(acc[mi][ni][2] + b0, acc[mi][ni][3] + b1);
        }
    }
}

// ---------------- fused MLP (2 linears) + LayerNorm + ReLU -------------------
// blocks [0,TU) = user tiles, [TU,TU+TI) = item tiles
#define FM_W0HI 0
#define FM_W0LO 32768
#define FM_W1HI 65536
#define FM_W1LO 98304
#define FM_AHI  131072
#define FM_ALO  163840
#define FM_PAR  196608        // bias0,bias1,lng,lnb : 4 x 512B
#define FM_TOT  (196608 + 2048)

__global__ __launch_bounds__(256) void fused_mlp(
    const float* __restrict__ agg_u, const float* __restrict__ agg_i,
    const unsigned* __restrict__ Whi, const unsigned* __restrict__ Wlo,
    int slot_u0, int slot_i0,
    const float* __restrict__ Bu0, const float* __restrict__ Bu1,
    const float* __restrict__ Bi0, const float* __restrict__ Bi1,
    const float* __restrict__ lngu, const float* __restrict__ lnbu,
    const float* __restrict__ lngi, const float* __restrict__ lnbi,
    float* __restrict__ out_u, float* __restrict__ out_i) {
    extern __shared__ char sm[];
    const int tid = threadIdx.x, wid = tid >> 5, lane = tid & 31;
    const bool user = blockIdx.x < TU;
    const int tile = user ? blockIdx.x : blockIdx.x - TU;
    const int M = user ? NU : NI;
    const int row0 = tile * 128;
    const float* A = user ? agg_u : agg_i;
    const int s0 = user ? slot_u0 : slot_i0;
    const float* B0 = user ? Bu0 : Bi0;
    const float* B1 = user ? Bu1 : Bi1;
    const float* lg = user ? lngu : lngi;
    const float* lb = user ? lnbu : lnbi;
    float* Y = user ? out_u : out_i;

    load_w32k(Whi + (size_t)s0 * 8192, sm + FM_W0HI, tid);
    load_w32k(Wlo + (size_t)s0 * 8192, sm + FM_W0LO, tid);
    load_w32k(Whi + (size_t)(s0 + 1) * 8192, sm + FM_W1HI, tid);
    load_w32k(Wlo + (size_t)(s0 + 1) * 8192, sm + FM_W1LO, tid);
    load_a(A, row0, M, sm + FM_AHI, sm + FM_ALO, tid);
    if (tid < 128) {
        float* par = (float*)(sm + FM_PAR);
        par[tid] = B0[tid];
        par[128 + tid] = B1[tid];
        par[256 + tid] = lg[tid];
        par[384 + tid] = lb[tid];
    }
    __syncthreads();

    const int wm = wid & 1, wn = wid >> 1;
    const unsigned base = smem_u32(sm);
    const float* par = (const float*)(sm + FM_PAR);
    float acc[4][4][4];

    // ---- GEMM1 + bias0 + relu -> rewrite A tile (bf16 hi/lo) in SMEM ----
    do_gemm(base, FM_AHI, FM_ALO, FM_W0HI, FM_W0LO, wm, wn, lane, acc);
    __syncthreads();   // everyone done reading SMA before overwrite
#pragma unroll
    for (int mi = 0; mi < 4; mi++) {
        const int r0 = wm * 64 + mi * 16 + (lane >> 2);
#pragma unroll
        for (int ni = 0; ni < 4; ni++) {
            const int cb = wn * 32 + ni * 8 + (lane & 3) * 2;
            const float b0 = par[cb], b1 = par[cb + 1];
            float v0 = fmaxf(acc[mi][ni][0] + b0, 0.f);
            float v1 = fmaxf(acc[mi][ni][1] + b1, 0.f);
            float v2 = fmaxf(acc[mi][ni][2] + b0, 0.f);
            float v3 = fmaxf(acc[mi][ni][3] + b1, 0.f);
            const int boff0 = swz(r0, cb >> 3) * 16 + ((cb & 7) >> 1) * 4;
            const int boff1 = swz(r0 + 8, cb >> 3) * 16 + ((cb & 7) >> 1) * 4;
            unsigned hi = packbf(v0, v1);
            unsigned lo = packbf(v0 - bflo(hi), v1 - bfhi(hi));
            *(unsigned*)(sm + FM_AHI + boff0) = hi;
            *(unsigned*)(sm + FM_ALO + boff0) = lo;
            hi = packbf(v2, v3);
            lo = packbf(v2 - bflo(hi), v3 - bfhi(hi));
            *(unsigned*)(sm + FM_AHI + boff1) = hi;
            *(unsigned*)(sm + FM_ALO + boff1) = lo;
        }
    }
    __syncthreads();

    // ---- GEMM2 + bias1 + relu -> fp32 tile in SMEM (reuse A region) ----
    do_gemm(base, FM_AHI, FM_ALO, FM_W1HI, FM_W1LO, wm, wn, lane, acc);
    __syncthreads();   // done reading SMA (bf16) before fp32 overwrite
    float* ftile = (float*)(sm + FM_AHI);
#pragma unroll
    for (int mi = 0; mi < 4; mi++) {
        const int r0 = wm * 64 + mi * 16 + (lane >> 2);
#pragma unroll
        for (int ni = 0; ni < 4; ni++) {
            const int cb = wn * 32 + ni * 8 + (lane & 3) * 2;
            const float b0 = par[128 + cb], b1 = par[128 + cb + 1];
            *(float2*)&ftile[r0 * 128 + cb] =
                make_float2(fmaxf(acc[mi][ni][0] + b0, 0.f), fmaxf(acc[mi][ni][1] + b1, 0.f));
            *(float2*)&ftile[(r0 + 8) * 128 + cb] =
                make_float2(fmaxf(acc[mi][ni][2] + b0, 0.f), fmaxf(acc[mi][ni][3] + b1, 0.f));
        }
    }
    __syncthreads();

    // ---- LayerNorm + ReLU, warp per row, straight to global ----
    const float4 gv = *(const float4*)&par[256 + lane * 4];
    const float4 bv = *(const float4*)&par[384 + lane * 4];
#pragma unroll
    for (int k = 0; k < 16; k++) {
        const int r = wid * 16 + k;
        const int grow = row0 + r;
        if (grow >= M) break;
        const float4 v = *(const float4*)&ftile[r * 128 + lane * 4];
        float s = v.x + v.y + v.z + v.w;
#pragma unroll
        for (int o = 16; o > 0; o >>= 1) s += __shfl_xor_sync(0xffffffffu, s, o);
        float m = s * (1.0f / CH);
        float dx0 = v.x - m, dx1 = v.y - m, dx2 = v.z - m, dx3 = v.w - m;
        float ss = dx0 * dx0 + dx1 * dx1 + dx2 * dx2 + dx3 * dx3;
#pragma unroll
        for (int o = 16; o > 0; o >>= 1) ss += __shfl_xor_sync(0xffffffffu, ss, o);
        float inv = rsqrtf(ss * (1.0f / CH) + 1e-5f);
        float4 o4;
        o4.x = fmaxf(dx0 * inv * gv.x + bv.x, 0.0f);
        o4.y = fmaxf(dx1 * inv * gv.y + bv.y, 0.0f);
        o4.z = fmaxf(dx2 * inv * gv.z + bv.z, 0.0f);
        o4.w = fmaxf(dx3 * inv * gv.w + bv.w, 0.0f);
        *(float4*)(Y + (size_t)grow * CH + lane * 4) = o4;
    }
}

// ---------------- orchestration ---------------------------------------------
extern "C" void kernel_launch(void* const* d_in, const int* in_sizes, int n_in,
                              void* d_out, int out_size) {
    const float* x_user = (const float*)d_in[0];
    const float* x_item = (const float*)d_in[1];
    const float* W_init = (const float*)d_in[2];
    const float* b_init = (const float*)d_in[3];
    const float* mlp_W  = (const float*)d_in[4];
    const float* mlp_b  = (const float*)d_in[5];
    const float* eps    = (const float*)d_in[6];
    const float* ln_g   = (const float*)d_in[7];
    const float* ln_b   = (const float*)d_in[8];
    const int* edge_ui  = (const int*)d_in[9];
    const int* edge_iu  = (const int*)d_in[10];

    float *xu, *xi, *au, *ai;
    unsigned *Wh, *Wl;
    int *rp_u, *rp_i, *cnt_u, *cnt_i, *col_u, *col_i;
    cudaGetSymbolAddress((void**)&xu, g_xu);
    cudaGetSymbolAddress((void**)&xi, g_xi);
    cudaGetSymbolAddress((void**)&au, g_agg_u);
    cudaGetSymbolAddress((void**)&ai, g_agg_i);
    cudaGetSymbolAddress((void**)&Wh, g_W_hi);
    cudaGetSymbolAddress((void**)&Wl, g_W_lo);
    cudaGetSymbolAddress((void**)&rp_u, g_rp_u);
    cudaGetSymbolAddress((void**)&rp_i, g_rp_i);
    cudaGetSymbolAddress((void**)&cnt_u, g_cnt_u);
    cudaGetSymbolAddress((void**)&cnt_i, g_cnt_i);
    cudaGetSymbolAddress((void**)&col_u, g_col_u);
    cudaGetSymbolAddress((void**)&col_i, g_col_i);

    cudaFuncSetAttribute(init_gemm, cudaFuncAttributeMaxDynamicSharedMemorySize, IG_TOT);
    cudaFuncSetAttribute(fused_mlp, cudaFuncAttributeMaxDynamicSharedMemorySize, FM_TOT);

    const int eblk = (NE + 255) / 256;
    const int pall = ((NI + NU) * 32 + 255) / 256;

    // ---- CSR build (both directions) ----
    cudaMemsetAsync(cnt_u, 0, NU * sizeof(int), 0);
    cudaMemsetAsync(cnt_i, 0, NI * sizeof(int), 0);
    hist2<<<eblk, 256>>>(edge_ui, edge_iu, cnt_i, cnt_u);
    scan2<<<2, 1024>>>(cnt_i, rp_i, cnt_u, rp_u);
    fill2<<<eblk, 256>>>(edge_ui, edge_iu, cnt_i, cnt_u, col_i, col_u);

    // ---- weights: bf16 hi/lo split once ----
    convW<<<10, 256>>>(W_init, mlp_W, Wh, Wl);

    // ---- init projections (merged user+item) ----
    init_gemm<<<TU + TI, 256, IG_TOT>>>(x_user, x_item, Wh, Wl, b_init, xu, xi);

    for (int l = 0; l < NLAY; l++) {
        pull_all<<<pall, 256>>>(rp_i, col_i, rp_u, col_u, xu, xi, eps + l * 2, ai, au);

        const int si0 = 2 + (l * 2 + 0) * 2;   // item MLP slots (edge type 0)
        const int su0 = 2 + (l * 2 + 1) * 2;   // user MLP slots (edge type 1)
        const float* Bi0 = mlp_b + (size_t)((l * 2 + 0) * 2 + 0) * CH;
        const float* Bi1 = mlp_b + (size_t)((l * 2 + 0) * 2 + 1) * CH;
        const float* Bu0 = mlp_b + (size_t)((l * 2 + 1) * 2 + 0) * CH;
        const float* Bu1 = mlp_b + (size_t)((l * 2 + 1) * 2 + 1) * CH;

        float* ou = (l == NLAY - 1) ? (float*)d_out : xu;
        float* oi = (l == NLAY - 1) ? (float*)d_out + (size_t)NU * CH : xi;
        fused_mlp<<<TU + TI, 256, FM_TOT>>>(
            au, ai, Wh, Wl, su0, si0, Bu0, Bu1, Bi0, Bi1,
            ln_g + (l * 2 + 0) * CH, ln_b + (l * 2 + 0) * CH,
            ln_g + (l * 2 + 1) * CH, ln_b + (l * 2 + 1) * CH,
            ou, oi);
    }
}